// round 1
// baseline (speedup 1.0000x reference)
#include <cuda_runtime.h>
#include <math.h>

#define DD 32
#define MAXT 8
#define GROUP 64
#define CUTOFF_F 6.0f
#define PI_F 3.14159265358979323846f

// ---------------------------------------------------------------------------
// zero the whole output buffer (it is poisoned; force/av/virial/Etot are
// accumulated with atomics, so they must start at 0)
// ---------------------------------------------------------------------------
__global__ void zero_kernel(float* __restrict__ p, int nelem) {
    int i = blockIdx.x * blockDim.x + threadIdx.x;
    if (i < nelem) p[i] = 0.0f;
}

// fast, well-conditioned tanh: 2 MUFU (EX2 via __expf, RCP) + a few ALU
__device__ __forceinline__ float ftanh(float x) {
    float t = __expf(2.0f * x);
    return 1.0f - 2.0f / (t + 1.0f);
}

__device__ __forceinline__ float warp_sum(float v) {
    v += __shfl_xor_sync(0xffffffffu, v, 16);
    v += __shfl_xor_sync(0xffffffffu, v, 8);
    v += __shfl_xor_sync(0xffffffffu, v, 4);
    v += __shfl_xor_sync(0xffffffffu, v, 2);
    v += __shfl_xor_sync(0xffffffffu, v, 1);
    return v;
}

// flush per-thread virial (9) + Etot accumulator for batch cur_bi
__device__ __forceinline__ void flush_stats(float (&vir)[9], float& etot_acc,
                                            int cur_bi, float* __restrict__ outV,
                                            float* __restrict__ outEtot, int tid) {
    float tv[9];
#pragma unroll
    for (int q = 0; q < 9; q++) {
        tv[q] = warp_sum(vir[q]);
        vir[q] = 0.0f;
    }
    if ((tid & 31) == 0) {
#pragma unroll
        for (int q = 0; q < 9; q++)
            atomicAdd(&outV[cur_bi * 9 + q], tv[q]);
    }
    if (tid == 0) {
        atomicAdd(&outEtot[cur_bi], etot_acc);
    }
    etot_acc = 0.0f;
}

// ---------------------------------------------------------------------------
// Main kernel: one 64-thread block processes a contiguous chunk of atoms.
// Thread j <-> neighbor j. Warp0 handles the per-atom 32-wide head.
// ---------------------------------------------------------------------------
__global__ __launch_bounds__(GROUP) void field_kernel(
    const int* __restrict__ element_map,      // (b,n)
    const int* __restrict__ neighbor_indices, // (b,n,m)
    const int* __restrict__ neighbor_types,   // (b,n,m)
    const float4* __restrict__ neighbor_vectors, // (b,n,m,4)
    const float* __restrict__ type_embed,     // (nt,32)
    const float* __restrict__ elem_bias,      // (nt,)
    const float* __restrict__ W1,             // (4,32)
    const float* __restrict__ b1,             // (32,)
    const float* __restrict__ W2,             // (32,32)
    const float* __restrict__ b2,             // (32,)
    const float* __restrict__ W3,             // (32,1)
    const float* __restrict__ b3,             // (1,)
    float* __restrict__ out,
    int b, int n, int m, int ntypes, int apb)
{
    __shared__ float W1s[4][DD];
    __shared__ float b1s[DD], b2s[DD], W3s[DD];
    __shared__ float tes[MAXT][DD];
    __shared__ float W2s[DD][DD];    // [k][l] : lane l reads column-contig
    __shared__ float W2Ts[DD][DD];   // [l][k] : lane k reads column-contig
    __shared__ float hsh[GROUP][DD + 1];  // stride 33 -> conflict free
    __shared__ float gsh[DD];
    __shared__ float dh2sh[DD];
    __shared__ float dhsh[DD];

    const int tid = threadIdx.x;

    // ---- load weights into shared (once per block) ----
    for (int idx = tid; idx < DD * DD; idx += GROUP) {
        float w = W2[idx];
        int k = idx >> 5, l = idx & 31;
        W2s[k][l]  = w;
        W2Ts[l][k] = w;
    }
    for (int idx = tid; idx < 4 * DD; idx += GROUP)
        W1s[idx >> 5][idx & 31] = W1[idx];
    if (tid < DD) {
        b1s[tid] = b1[tid];
        b2s[tid] = b2[tid];
        W3s[tid] = W3[tid];
    }
    for (int idx = tid; idx < ntypes * DD; idx += GROUP)
        tes[idx / DD][idx % DD] = type_embed[idx];
    __syncthreads();

    const long total = (long)b * n;
    const long start = (long)blockIdx.x * apb;
    long end = start + apb;
    if (end > total) end = total;
    if (start >= total) return;

    // output layout: [Etot(b), Ei(bn), force(3bn), virial(9b), av(9bn)]
    float* outEtot = out;
    float* outEi   = out + b;
    float* outF    = out + b + total;
    float* outV    = out + b + 4 * total;
    float* outAV   = out + 10L * b + 4 * total;

    const float invC  = PI_F / CUTOFF_F;
    const float b3v   = __ldg(b3);
    const float inv_m = 1.0f / (float)m;

    float vir[9];
#pragma unroll
    for (int q = 0; q < 9; q++) vir[q] = 0.0f;
    float etot_acc = 0.0f;
    int cur_bi = -1;

    for (long atom = start; atom < end; ++atom) {
        const int bi = (int)(atom / n);
        const int ai = (int)(atom - (long)bi * n);

        if (bi != cur_bi) {
            if (cur_bi >= 0)
                flush_stats(vir, etot_acc, cur_bi, outV, outEtot, tid);
            cur_bi = bi;
        }

        // ------------------ forward (per neighbor) ------------------
        const int j = tid;
        const bool valid = (j < m);
        const long base = atom * m + j;

        float rx = 0.f, ry = 0.f, rz = 0.f;
        float s = 0.f, e = 0.f, fc = 0.f, d = 0.f, inv_d = 0.f;
        float h[DD];

        if (valid) {
            float4 nv = __ldg(&neighbor_vectors[base]);
            rx = nv.y; ry = nv.z; rz = nv.w;
            int tt = __ldg(&neighbor_types[base]);
            float r2 = rx * rx + ry * ry + rz * rz;
            inv_d = rsqrtf(r2);
            d = r2 * inv_d;
            float dm = fminf(d, CUTOFF_F);
            fc = 0.5f * (__cosf(dm * invC) + 1.0f);
            e = __expf(-d);
            s = e * fc;
            float sx = s * rx, sy = s * ry, sz = s * rz;
#pragma unroll
            for (int k = 0; k < DD; k++) {
                float pre = b1s[k] + tes[tt][k];
                pre = fmaf(s,  W1s[0][k], pre);
                pre = fmaf(sx, W1s[1][k], pre);
                pre = fmaf(sy, W1s[2][k], pre);
                pre = fmaf(sz, W1s[3][k], pre);
                h[k] = ftanh(pre);
            }
        } else {
#pragma unroll
            for (int k = 0; k < DD; k++) h[k] = 0.0f;
        }
#pragma unroll
        for (int k = 0; k < DD; k++) hsh[j][k] = h[k];
        __syncthreads();

        // ------------------ per-atom head (warp 0) ------------------
        if (tid < 32) {
            float a0 = 0.f, a1 = 0.f, a2 = 0.f, a3 = 0.f;
#pragma unroll
            for (int j2 = 0; j2 < GROUP; j2 += 4) {
                a0 += hsh[j2 + 0][tid];
                a1 += hsh[j2 + 1][tid];
                a2 += hsh[j2 + 2][tid];
                a3 += hsh[j2 + 3][tid];
            }
            float g = (a0 + a1) + (a2 + a3);
            g *= inv_m;
            gsh[tid] = g;
            __syncwarp();

            float c0 = b2s[tid], c1 = 0.f;
#pragma unroll
            for (int k = 0; k < DD; k += 2) {
                c0 = fmaf(gsh[k],     W2s[k][tid],     c0);
                c1 = fmaf(gsh[k + 1], W2s[k + 1][tid], c1);
            }
            float h2 = ftanh(c0 + c1);
            float w3 = W3s[tid];

            float v = warp_sum(h2 * w3);
            if (tid == 0) {
                float Ei = v + b3v + __ldg(&elem_bias[__ldg(&element_map[atom])]);
                outEi[atom] = Ei;
                etot_acc += Ei;
            }

            float dh2 = (1.0f - h2 * h2) * w3;
            dh2sh[tid] = dh2;
            __syncwarp();

            float d0 = 0.f, d1 = 0.f;
#pragma unroll
            for (int l = 0; l < DD; l += 2) {
                d0 = fmaf(W2Ts[l][tid],     dh2sh[l],     d0);
                d1 = fmaf(W2Ts[l + 1][tid], dh2sh[l + 1], d1);
            }
            dhsh[tid] = (d0 + d1) * inv_m;
        }
        __syncthreads();

        // ------------------ backward (per neighbor) ------------------
        float gx = 0.f, gy = 0.f, gz = 0.f;
        if (valid) {
            float f0 = 0.f, f1 = 0.f, f2 = 0.f, f3 = 0.f;
#pragma unroll
            for (int k = 0; k < DD; k++) {
                float dpre = dhsh[k] * (1.0f - h[k] * h[k]);
                f0 = fmaf(W1s[0][k], dpre, f0);
                f1 = fmaf(W1s[1][k], dpre, f1);
                f2 = fmaf(W1s[2][k], dpre, f2);
                f3 = fmaf(W1s[3][k], dpre, f3);
            }
            float ds = f0 + rx * f1 + ry * f2 + rz * f3;
            float fcp = (d < CUTOFF_F) ? (-0.5f * invC * __sinf(d * invC)) : 0.0f;
            float dd = ds * (e * (fcp - fc));
            float t = dd * inv_d;
            gx = fmaf(t, rx, s * f1);
            gy = fmaf(t, ry, s * f2);
            gz = fmaf(t, rz, s * f3);

            float pv[9];
            pv[0] = rx * gx; pv[1] = rx * gy; pv[2] = rx * gz;
            pv[3] = ry * gx; pv[4] = ry * gy; pv[5] = ry * gz;
            pv[6] = rz * gx; pv[7] = rz * gy; pv[8] = rz * gz;
#pragma unroll
            for (int q = 0; q < 9; q++) vir[q] += pv[q];

            int ni = __ldg(&neighbor_indices[base]);
            if (ni < n) {
                float* fr = &outF[((long)bi * n + ni) * 3];
                atomicAdd(fr + 0, -gx);
                atomicAdd(fr + 1, -gy);
                atomicAdd(fr + 2, -gz);
                float* ar = &outAV[((long)bi * n + ni) * 9];
#pragma unroll
                for (int q = 0; q < 9; q++) atomicAdd(ar + q, pv[q]);
            }
        }

        // central-atom force: sum grad over all neighbors of this atom
        float cx = warp_sum(gx);
        float cy = warp_sum(gy);
        float cz = warp_sum(gz);
        if ((tid & 31) == 0) {
            float* fr = &outF[((long)bi * n + ai) * 3];
            atomicAdd(fr + 0, cx);
            atomicAdd(fr + 1, cy);
            atomicAdd(fr + 2, cz);
        }
        // hsh/dhsh reuse next iteration is ordered by the two __syncthreads
    }

    if (cur_bi >= 0)
        flush_stats(vir, etot_acc, cur_bi, outV, outEtot, tid);
}

// ---------------------------------------------------------------------------
extern "C" void kernel_launch(void* const* d_in, const int* in_sizes, int n_in,
                              void* d_out, int out_size) {
    const int*    element_map      = (const int*)d_in[0];
    // d_in[1] central_atoms: unused by the reference
    const int*    neighbor_indices = (const int*)d_in[2];
    const int*    neighbor_types   = (const int*)d_in[3];
    const float4* neighbor_vectors = (const float4*)d_in[4];
    // d_in[5] n_ghost: not needed (we only scatter to rows < n)
    const float*  type_embed = (const float*)d_in[6];
    const float*  elem_bias  = (const float*)d_in[7];
    const float*  W1 = (const float*)d_in[8];
    const float*  b1 = (const float*)d_in[9];
    const float*  W2 = (const float*)d_in[10];
    const float*  b2 = (const float*)d_in[11];
    const float*  W3 = (const float*)d_in[12];
    const float*  b3 = (const float*)d_in[13];
    float* out = (float*)d_out;

    const int bn  = in_sizes[0];          // b*n
    const int bnm = in_sizes[2];          // b*n*m
    const int m   = bnm / bn;
    const int ntypes = in_sizes[7];
    // out_size = b(Etot) + bn(Ei) + 3bn(force) + 9b(virial) + 9bn(av) = 10b + 13bn
    int b = (int)(((long)out_size - 13L * bn) / 10L);
    if (b < 1) b = 1;
    const int n = bn / b;

    // zero outputs (all accumulated regions; Ei is overwritten anyway)
    {
        int threads = 256;
        int blocks = (out_size + threads - 1) / threads;
        zero_kernel<<<blocks, threads>>>(out, out_size);
    }

    // main kernel: 64-thread blocks, contiguous atom chunks
    int apb = (bn + 2047) / 2048;
    if (apb < 1) apb = 1;
    int grid = (bn + apb - 1) / apb;
    field_kernel<<<grid, GROUP>>>(element_map, neighbor_indices, neighbor_types,
                                  neighbor_vectors, type_embed, elem_bias,
                                  W1, b1, W2, b2, W3, b3,
                                  out, b, n, m, ntypes, apb);
}

// round 2
// speedup vs baseline: 1.2333x; 1.2333x over previous
#include <cuda_runtime.h>
#include <math.h>

#define DD 32
#define NWARP 4
#define APW 4
#define HSTRIDE 65
#define CUTOFF_F 6.0f
#define PI_F 3.14159265358979323846f
#define FULLMASK 0xffffffffu

// 12 floats (3 x float4) per (batch,atom) row: [pv0..pv8, fx, fy, fz]
__device__ float4 g_scratch[32768 * 3];

// ---------------------------------------------------------------------------
__global__ void zero_kernel(float* __restrict__ out, int nout, int nscratch) {
    int i = blockIdx.x * blockDim.x + threadIdx.x;
    if (i < nout) out[i] = 0.0f;
    float* s = (float*)g_scratch;
    if (i < nscratch) s[i] = 0.0f;
}

// scatter scratch -> final force / atomic-virial layout
__global__ void pack_kernel(float* __restrict__ out, int b, int bn) {
    int i = blockIdx.x * blockDim.x + threadIdx.x;
    if (i >= bn) return;
    const float* row = (const float*)(g_scratch + (long)i * 3);
    float* outF  = out + b + bn + (long)i * 3;
    float* outAV = out + 10L * b + 4L * bn + (long)i * 9;
#pragma unroll
    for (int q = 0; q < 9; q++) outAV[q] = row[q];
    outF[0] = row[9]; outF[1] = row[10]; outF[2] = row[11];
}

// ---------------------------------------------------------------------------
__device__ __forceinline__ float ftanh(float x) {
    float t = __expf(2.0f * x);
    return 1.0f - 2.0f / (t + 1.0f);
}
__device__ __forceinline__ float warp_sum(float v) {
#pragma unroll
    for (int o = 16; o; o >>= 1) v += __shfl_xor_sync(FULLMASK, v, o);
    return v;
}
__device__ __forceinline__ void red_add_v4(float* p, float a, float b, float c, float d) {
    asm volatile("red.global.add.v4.f32 [%0], {%1,%2,%3,%4};"
                 :: "l"(p), "f"(a), "f"(b), "f"(c), "f"(d) : "memory");
}

// per-warp stat flush: 9 virial components + Etot for batch cur_bi
__device__ __forceinline__ void flush_stats(float (&vir)[9], float& etot, int cur_bi,
                                            float* __restrict__ outV,
                                            float* __restrict__ outEtot, int lane) {
    float tv[9];
#pragma unroll
    for (int q = 0; q < 9; q++) { tv[q] = warp_sum(vir[q]); vir[q] = 0.0f; }
    if (lane == 0) {
#pragma unroll
        for (int q = 0; q < 9; q++) atomicAdd(&outV[cur_bi * 9 + q], tv[q]);
        atomicAdd(&outEtot[cur_bi], etot);
    }
    etot = 0.0f;
}

// ---------------------------------------------------------------------------
// warp-per-atom: lane = channel (fwd/head) and lane = neighbor-pair (P0/bwd)
// ---------------------------------------------------------------------------
__global__ __launch_bounds__(NWARP * 32) void field_kernel(
    const int* __restrict__ element_map,
    const int* __restrict__ neighbor_indices,
    const int* __restrict__ neighbor_types,
    const float4* __restrict__ neighbor_vectors,
    const float* __restrict__ type_embed,
    const float* __restrict__ elem_bias,
    const float* __restrict__ W1, const float* __restrict__ b1,
    const float* __restrict__ W2, const float* __restrict__ b2,
    const float* __restrict__ W3, const float* __restrict__ b3,
    float* __restrict__ out,
    int b, int n, int m, int ntypes)
{
    __shared__ float W2s[DD][DD + 1];                  // [k][l]
    __shared__ __align__(16) float W1f[4 * DD];        // flat rows
    __shared__ float biassh[4][DD];                    // b1 + type_embed
    __shared__ float b2s[DD], W3s[DD];
    __shared__ float hshT[NWARP][DD * HSTRIDE];        // h transposed: [k][j]
    __shared__ float4 s4sh[NWARP][64];                 // (s, s*rx, s*ry, s*rz)
    __shared__ int   ttsh[NWARP][64];
    __shared__ __align__(16) float dhshf[NWARP][DD];

    const int tid  = threadIdx.x;
    const int wid  = tid >> 5;
    const int lane = tid & 31;

    for (int idx = tid; idx < DD * DD; idx += NWARP * 32)
        W2s[idx >> 5][idx & 31] = W2[idx];
    for (int idx = tid; idx < 4 * DD; idx += NWARP * 32)
        W1f[idx] = W1[idx];
    for (int idx = tid; idx < ntypes * DD; idx += NWARP * 32)
        biassh[idx / DD][idx % DD] = b1[idx % DD] + type_embed[idx];
    if (tid < DD) { b2s[tid] = b2[tid]; W3s[tid] = W3[tid]; }
    __syncthreads();

    // per-lane (channel) register weights
    const float w10 = W1f[lane], w11 = W1f[DD + lane],
                w12 = W1f[2 * DD + lane], w13 = W1f[3 * DD + lane];
    const float biasr0 = biassh[0][lane];
    const float biasr1 = (ntypes > 1) ? biassh[1][lane] : 0.0f;
    const float biasr2 = (ntypes > 2) ? biassh[2][lane] : 0.0f;
    const float b2k = b2s[lane], w3k = W3s[lane];
    const float b3v = __ldg(b3);
    const float invC = PI_F / CUTOFF_F;
    const float inv_m = 1.0f / (float)m;

    const long total = (long)b * n;
    float* outEtot = out;
    float* outEi   = out + b;
    float* outV    = out + b + 4 * total;

    const long gw = (long)blockIdx.x * NWARP + wid;
    long a0 = gw * APW;
    long a1 = a0 + APW; if (a1 > total) a1 = total;

    float vir[9];
#pragma unroll
    for (int q = 0; q < 9; q++) vir[q] = 0.0f;
    float etot = 0.0f;
    int cur_bi = -1;

    const float4* W1v = (const float4*)W1f;

    for (long atom = a0; atom < a1; ++atom) {
        const int bi = (int)(atom / n);
        const int ai = (int)(atom - (long)bi * n);
        if (bi != cur_bi) {
            if (cur_bi >= 0) flush_stats(vir, etot, cur_bi, outV, outEtot, lane);
            cur_bi = bi;
        }

        // ---- P0: per-neighbor scalars (lane owns j=lane, j=lane+32) ----
        float rxr[2], ryr[2], rzr[2], sr[2], er[2], fcr[2], dr[2], idr[2];
        int nir[2];
#pragma unroll
        for (int nb = 0; nb < 2; nb++) {
            int j = lane + nb * 32;
            bool valid = (j < m);
            long base = atom * m + j;
            float4 nv = valid ? __ldg(&neighbor_vectors[base]) : make_float4(0,0,0,0);
            int tt   = valid ? __ldg(&neighbor_types[base]) : 0;
            nir[nb]  = valid ? __ldg(&neighbor_indices[base]) : 0x7fffffff;
            float rx = nv.y, ry = nv.z, rz = nv.w;
            float r2 = rx * rx + ry * ry + rz * rz;
            float inv_d = rsqrtf(r2);
            float d = r2 * inv_d;
            float fc = 0.5f * (__cosf(fminf(d, CUTOFF_F) * invC) + 1.0f);
            float e = __expf(-d);
            float s = e * fc;
            if (!valid) { s = 0.0f; d = 0.0f; inv_d = 0.0f; e = 0.0f; fc = 0.0f; }
            s4sh[wid][j] = make_float4(s, s * rx, s * ry, s * rz);
            ttsh[wid][j] = tt;
            rxr[nb] = rx; ryr[nb] = ry; rzr[nb] = rz;
            sr[nb] = s; er[nb] = e; fcr[nb] = fc; dr[nb] = d; idr[nb] = inv_d;
        }
        __syncwarp();

        // ---- P1: forward, channel-per-lane; g accumulates in-lane ----
        float g = 0.0f;
#pragma unroll 16
        for (int j = 0; j < 64; j++) {
            float4 sv = s4sh[wid][j];
            int tt = ttsh[wid][j];
            float bias = (tt == 0) ? biasr0 : ((tt == 1) ? biasr1 : biasr2);
            float pre = fmaf(sv.x, w10, bias);
            pre = fmaf(sv.y, w11, pre);
            pre = fmaf(sv.z, w12, pre);
            pre = fmaf(sv.w, w13, pre);
            float h = ftanh(pre);
            hshT[wid][lane * HSTRIDE + j] = h;
            if (j < m) g += h;
        }

        // ---- P2: head (lane = channel), g/dh2 broadcast via shuffles ----
        float gm = g * inv_m;
        float c = b2k;
#pragma unroll
        for (int l = 0; l < DD; l++) {
            float gl = __shfl_sync(FULLMASK, gm, l);
            c = fmaf(gl, W2s[l][lane], c);
        }
        float h2 = ftanh(c);
        float val = h2 * w3k;
        float esum = warp_sum(val);
        if (lane == 0) {
            int em = __ldg(&element_map[atom]);
            float Ei = esum + b3v + __ldg(&elem_bias[em]);
            outEi[atom] = Ei;
            etot += Ei;
        }
        float dh2 = (1.0f - h2 * h2) * w3k;
        float dg = 0.0f;
#pragma unroll
        for (int l = 0; l < DD; l++) {
            float dl = __shfl_sync(FULLMASK, dh2, l);
            dg = fmaf(W2s[lane][l], dl, dg);
        }
        dhshf[wid][lane] = dg * inv_m;
        __syncwarp();

        // ---- P3: backward, neighbor-per-lane ----
        const float4* dhv = (const float4*)dhshf[wid];
        float cgx = 0.0f, cgy = 0.0f, cgz = 0.0f;
#pragma unroll
        for (int nb = 0; nb < 2; nb++) {
            int j = lane + nb * 32;
            if (j < m) {
                float f0 = 0.f, f1 = 0.f, f2 = 0.f, f3 = 0.f;
#pragma unroll
                for (int kq = 0; kq < 8; kq++) {
                    float4 dh4 = dhv[kq];
                    float4 wa = W1v[kq], wb = W1v[8 + kq], wc = W1v[16 + kq], wd = W1v[24 + kq];
                    const float* hb = &hshT[wid][(kq * 4) * HSTRIDE + j];
                    float h, t, dp;
                    h = hb[0];           t = fmaf(-h, h, 1.0f); dp = dh4.x * t;
                    f0 = fmaf(wa.x, dp, f0); f1 = fmaf(wb.x, dp, f1);
                    f2 = fmaf(wc.x, dp, f2); f3 = fmaf(wd.x, dp, f3);
                    h = hb[HSTRIDE];     t = fmaf(-h, h, 1.0f); dp = dh4.y * t;
                    f0 = fmaf(wa.y, dp, f0); f1 = fmaf(wb.y, dp, f1);
                    f2 = fmaf(wc.y, dp, f2); f3 = fmaf(wd.y, dp, f3);
                    h = hb[2 * HSTRIDE]; t = fmaf(-h, h, 1.0f); dp = dh4.z * t;
                    f0 = fmaf(wa.z, dp, f0); f1 = fmaf(wb.z, dp, f1);
                    f2 = fmaf(wc.z, dp, f2); f3 = fmaf(wd.z, dp, f3);
                    h = hb[3 * HSTRIDE]; t = fmaf(-h, h, 1.0f); dp = dh4.w * t;
                    f0 = fmaf(wa.w, dp, f0); f1 = fmaf(wb.w, dp, f1);
                    f2 = fmaf(wc.w, dp, f2); f3 = fmaf(wd.w, dp, f3);
                }
                float rx = rxr[nb], ry = ryr[nb], rz = rzr[nb];
                float s = sr[nb], e = er[nb], fc = fcr[nb], d = dr[nb], inv_d = idr[nb];
                float ds = f0 + rx * f1 + ry * f2 + rz * f3;
                float fcp = (d < CUTOFF_F) ? (-0.5f * invC * __sinf(d * invC)) : 0.0f;
                float dd = ds * (e * (fcp - fc));
                float t2 = dd * inv_d;
                float gx = fmaf(t2, rx, s * f1);
                float gy = fmaf(t2, ry, s * f2);
                float gz = fmaf(t2, rz, s * f3);

                float pv0 = rx * gx, pv1 = rx * gy, pv2 = rx * gz;
                float pv3 = ry * gx, pv4 = ry * gy, pv5 = ry * gz;
                float pv6 = rz * gx, pv7 = rz * gy, pv8 = rz * gz;
                vir[0] += pv0; vir[1] += pv1; vir[2] += pv2;
                vir[3] += pv3; vir[4] += pv4; vir[5] += pv5;
                vir[6] += pv6; vir[7] += pv7; vir[8] += pv8;
                cgx += gx; cgy += gy; cgz += gz;

                int ni = nir[nb];
                if (ni < n) {
                    float* p = (float*)(g_scratch + ((long)bi * n + ni) * 3);
                    red_add_v4(p,     pv0, pv1, pv2, pv3);
                    red_add_v4(p + 4, pv4, pv5, pv6, pv7);
                    red_add_v4(p + 8, pv8, -gx, -gy, -gz);
                }
            }
        }
        // central-atom force -> scratch row ai (slots 9..11; slot 8 gets +0)
        float cx = warp_sum(cgx), cy = warp_sum(cgy), cz = warp_sum(cgz);
        if (lane == 0) {
            float* p = (float*)(g_scratch + ((long)bi * n + ai) * 3);
            red_add_v4(p + 8, 0.0f, cx, cy, cz);
        }
    }

    if (cur_bi >= 0) flush_stats(vir, etot, cur_bi, outV, outEtot, lane);
}

// ---------------------------------------------------------------------------
extern "C" void kernel_launch(void* const* d_in, const int* in_sizes, int n_in,
                              void* d_out, int out_size) {
    const int*    element_map      = (const int*)d_in[0];
    const int*    neighbor_indices = (const int*)d_in[2];
    const int*    neighbor_types   = (const int*)d_in[3];
    const float4* neighbor_vectors = (const float4*)d_in[4];
    const float*  type_embed = (const float*)d_in[6];
    const float*  elem_bias  = (const float*)d_in[7];
    const float*  W1 = (const float*)d_in[8];
    const float*  b1 = (const float*)d_in[9];
    const float*  W2 = (const float*)d_in[10];
    const float*  b2 = (const float*)d_in[11];
    const float*  W3 = (const float*)d_in[12];
    const float*  b3 = (const float*)d_in[13];
    float* out = (float*)d_out;

    const int bn  = in_sizes[0];
    const int bnm = in_sizes[2];
    const int m   = bnm / bn;
    const int ntypes = in_sizes[7];
    int b = (int)(((long)out_size - 13L * bn) / 10L);
    if (b < 1) b = 1;
    const int n = bn / b;

    const int nscratch = bn * 12;
    {
        int nmax = out_size > nscratch ? out_size : nscratch;
        int threads = 256;
        zero_kernel<<<(nmax + threads - 1) / threads, threads>>>(out, out_size, nscratch);
    }

    int atoms_per_block = NWARP * APW;
    int grid = (bn + atoms_per_block - 1) / atoms_per_block;
    field_kernel<<<grid, NWARP * 32>>>(element_map, neighbor_indices, neighbor_types,
                                       neighbor_vectors, type_embed, elem_bias,
                                       W1, b1, W2, b2, W3, b3,
                                       out, b, n, m, ntypes);

    pack_kernel<<<(bn + 255) / 256, 256>>>(out, b, bn);
}